// round 5
// baseline (speedup 1.0000x reference)
// QuantizedLinear: out = scale * (x @ qw^T) + bias_scale * q_bias
// M=8192, K=4096, N=16384, fp32 in/out, int32 (int8-valued) weights.
//
// sm_103 BASELINE toolchain (no 'a' features): tcgen05 is rejected by ptxas,
// so this uses ldmatrix + mma.sync.m16n8k16.bf16 (legacy HMMA path).
// Numerics: weights exact in bf16; x split into hi/lo bf16, two MMA passes
// accumulated in fp32 registers -> rel err ~1e-5.
#include <cuda_runtime.h>
#include <cuda_bf16.h>
#include <cstdint>

// ---------------- problem constants ----------------
constexpr int Mdim = 8192;
constexpr int Ndim = 16384;
constexpr int Kdim = 4096;

constexpr int BM = 128;
constexpr int BN = 128;
constexpr int BK = 64;              // 64 bf16 = 128B = one swizzle row
constexpr int STAGES = 3;
constexpr int NKT = Kdim / BK;      // 64 k-iterations

// SMEM layout (dynamic)
constexpr int OFF_BIAS  = 0;        // 128 floats
constexpr int OFF_STAGE = 1024;
constexpr int STAGE_STRIDE = 49152; // A_hi 16K | A_lo 16K | B 16K
constexpr int A_HI_OFF = 0;
constexpr int A_LO_OFF = 16384;
constexpr int B_OFF    = 32768;
constexpr int SMEM_TOTAL = OFF_STAGE + STAGES * STAGE_STRIDE; // 148480

// ---------------- device scratch (no cudaMalloc allowed) ----------------
__device__ uint4 g_wb4 [(size_t)Ndim * Kdim * 2 / 16]; // 128MB bf16 weights
__device__ uint4 g_xhi4[(size_t)Mdim * Kdim * 2 / 16]; //  64MB bf16 x-hi
__device__ uint4 g_xlo4[(size_t)Mdim * Kdim * 2 / 16]; //  64MB bf16 x-lo

// ---------------- helpers ----------------
__device__ __forceinline__ uint32_t smem_u32(const void* p) {
    uint32_t a;
    asm("{ .reg .u64 t; cvta.to.shared.u64 t, %1; cvt.u32.u64 %0, t; }" : "=r"(a) : "l"(p));
    return a;
}
// 128B-row swizzle: XOR 16B-chunk index with (row & 7)
__device__ __forceinline__ uint32_t swz(uint32_t byte_off) {
    return byte_off ^ ((byte_off >> 3) & 0x70);
}
__device__ __forceinline__ void cp16(uint32_t dst, const void* src) {
    asm volatile("cp.async.cg.shared.global [%0], [%1], 16;" :: "r"(dst), "l"(src) : "memory");
}
__device__ __forceinline__ void cp_commit() {
    asm volatile("cp.async.commit_group;" ::: "memory");
}
__device__ __forceinline__ void cp_wait1() {
    asm volatile("cp.async.wait_group 1;" ::: "memory");
}
__device__ __forceinline__ void ldsm_x4(uint32_t r[4], uint32_t addr) {
    asm volatile("ldmatrix.sync.aligned.m8n8.x4.shared.b16 {%0,%1,%2,%3}, [%4];"
                 : "=r"(r[0]), "=r"(r[1]), "=r"(r[2]), "=r"(r[3]) : "r"(addr));
}
__device__ __forceinline__ void mma16816(float c[4], const uint32_t a[4], const uint32_t b[2]) {
    asm volatile(
        "mma.sync.aligned.m16n8k16.row.col.f32.bf16.bf16.f32 "
        "{%0,%1,%2,%3}, {%4,%5,%6,%7}, {%8,%9}, {%0,%1,%2,%3};"
        : "+f"(c[0]), "+f"(c[1]), "+f"(c[2]), "+f"(c[3])
        : "r"(a[0]), "r"(a[1]), "r"(a[2]), "r"(a[3]), "r"(b[0]), "r"(b[1]));
}

// ---------------- preconvert kernels ----------------
__global__ void convert_w_kernel(const int* __restrict__ qw) {
    __nv_bfloat162* wb2 = reinterpret_cast<__nv_bfloat162*>(g_wb4);
    const int4* qw4 = reinterpret_cast<const int4*>(qw);
    const size_t n4 = (size_t)Ndim * Kdim / 4;
    size_t stride = (size_t)gridDim.x * blockDim.x;
    for (size_t i = (size_t)blockIdx.x * blockDim.x + threadIdx.x; i < n4; i += stride) {
        int4 v = qw4[i];
        __nv_bfloat162 a, b;
        a.x = __float2bfloat16_rn((float)v.x);
        a.y = __float2bfloat16_rn((float)v.y);
        b.x = __float2bfloat16_rn((float)v.z);
        b.y = __float2bfloat16_rn((float)v.w);
        wb2[i * 2]     = a;
        wb2[i * 2 + 1] = b;
    }
}

__global__ void convert_x_kernel(const float* __restrict__ x) {
    __nv_bfloat162* xhi2 = reinterpret_cast<__nv_bfloat162*>(g_xhi4);
    __nv_bfloat162* xlo2 = reinterpret_cast<__nv_bfloat162*>(g_xlo4);
    const float4* x4 = reinterpret_cast<const float4*>(x);
    const size_t n4 = (size_t)Mdim * Kdim / 4;
    size_t stride = (size_t)gridDim.x * blockDim.x;
    for (size_t i = (size_t)blockIdx.x * blockDim.x + threadIdx.x; i < n4; i += stride) {
        float4 v = x4[i];
        __nv_bfloat16 hx = __float2bfloat16_rn(v.x);
        __nv_bfloat16 hy = __float2bfloat16_rn(v.y);
        __nv_bfloat16 hz = __float2bfloat16_rn(v.z);
        __nv_bfloat16 hw = __float2bfloat16_rn(v.w);
        __nv_bfloat162 hi0, hi1, lo0, lo1;
        hi0.x = hx; hi0.y = hy; hi1.x = hz; hi1.y = hw;
        lo0.x = __float2bfloat16_rn(v.x - __bfloat162float(hx));
        lo0.y = __float2bfloat16_rn(v.y - __bfloat162float(hy));
        lo1.x = __float2bfloat16_rn(v.z - __bfloat162float(hz));
        lo1.y = __float2bfloat16_rn(v.w - __bfloat162float(hw));
        xhi2[i * 2]     = hi0;
        xhi2[i * 2 + 1] = hi1;
        xlo2[i * 2]     = lo0;
        xlo2[i * 2 + 1] = lo1;
    }
}

// ---------------- main GEMM kernel ----------------
__global__ void __launch_bounds__(256, 1)
gemm_kernel(const int* __restrict__ qbias,
            const float* __restrict__ scale_p,
            const float* __restrict__ bscale_p,
            float* __restrict__ out) {
    extern __shared__ char smem[];
    const uint32_t sbase = smem_u32(smem);
    const int tid  = threadIdx.x;
    const int wid  = tid >> 5;
    const int lane = tid & 31;
    const int wm = wid >> 2;   // 0..1  -> 64-row M slab
    const int wn = wid & 3;    // 0..3  -> 32-col N slab

    const __nv_bfloat16* xhi = reinterpret_cast<const __nv_bfloat16*>(g_xhi4);
    const __nv_bfloat16* xlo = reinterpret_cast<const __nv_bfloat16*>(g_xlo4);
    const __nv_bfloat16* wb  = reinterpret_cast<const __nv_bfloat16*>(g_wb4);

    const int n0 = blockIdx.x * BN;
    const int m0 = blockIdx.y * BM;

    // bias staging: biasS[j] = bias_scale * q_bias[n0 + j]
    {
        float bsc = bscale_p[0];
        float* sb = reinterpret_cast<float*>(smem + OFF_BIAS);
        for (int i = tid; i < BN; i += 256)
            sb[i] = bsc * (float)qbias[n0 + i];
    }

    // -------- per-thread producer address precompute --------
    // Each tile = 128 rows x 8 chunks of 16B = 1024 chunks; 256 threads x 4.
    const __nv_bfloat16* pAh[4];
    const __nv_bfloat16* pAl[4];
    const __nv_bfloat16* pBp[4];
    uint32_t dA[4], dB[4];
    #pragma unroll
    for (int i = 0; i < 4; i++) {
        int q = i * 256 + tid;
        int row = q >> 3, ch = q & 7;
        dA[i] = swz((uint32_t)(row * 128 + ch * 16));
        dB[i] = dA[i];
        pAh[i] = xhi + (size_t)(m0 + row) * Kdim + ch * 8;
        pAl[i] = xlo + (size_t)(m0 + row) * Kdim + ch * 8;
        pBp[i] = wb  + (size_t)(n0 + row) * Kdim + ch * 8;
    }

    // -------- accumulators --------
    float acc[4][4][4];
    #pragma unroll
    for (int mi = 0; mi < 4; mi++)
        #pragma unroll
        for (int ni = 0; ni < 4; ni++)
            #pragma unroll
            for (int j = 0; j < 4; j++)
                acc[mi][ni][j] = 0.0f;

    // -------- prologue: prefetch stages 0..STAGES-2 --------
    #pragma unroll
    for (int s = 0; s < STAGES - 1; s++) {
        const uint32_t sb_ = sbase + OFF_STAGE + s * STAGE_STRIDE;
        const int k0 = s * BK;
        #pragma unroll
        for (int i = 0; i < 4; i++) {
            cp16(sb_ + A_HI_OFF + dA[i], pAh[i] + k0);
            cp16(sb_ + A_LO_OFF + dA[i], pAl[i] + k0);
            cp16(sb_ + B_OFF    + dB[i], pBp[i] + k0);
        }
        cp_commit();
    }

    // -------- mainloop --------
    const int mrow_base = wm * 64;
    const int nb_base   = wn * 32;

    // ldmatrix lane-invariant pieces
    const int a_row_in = lane & 15;           // row within 16-row chunk
    const int a_ksel   = lane >> 4;           // 0/1 -> which 16B of the k-step
    const int b_nrow_in = ((lane >> 4) << 3) + (lane & 7); // 0..15 within 16-n group
    const int b_ksel    = (lane >> 3) & 1;

    int st = 0;
    for (int kt = 0; kt < NKT; kt++) {
        cp_wait1();
        __syncthreads();

        // issue next stage's loads (into the stage consumed at kt-1)
        {
            int kt_next = kt + STAGES - 1;
            if (kt_next < NKT) {
                int stn = kt_next;
                stn = (st + STAGES - 1) % STAGES;          // == kt_next % STAGES
                const uint32_t sb_ = sbase + OFF_STAGE + stn * STAGE_STRIDE;
                const int k0 = kt_next * BK;
                #pragma unroll
                for (int i = 0; i < 4; i++) {
                    cp16(sb_ + A_HI_OFF + dA[i], pAh[i] + k0);
                    cp16(sb_ + A_LO_OFF + dA[i], pAl[i] + k0);
                    cp16(sb_ + B_OFF    + dB[i], pBp[i] + k0);
                }
            }
            cp_commit(); // always commit (possibly empty group) to keep wait counts aligned
        }

        // consume stage st
        const uint32_t sAhi = sbase + OFF_STAGE + st * STAGE_STRIDE + A_HI_OFF;
        const uint32_t sAlo = sbase + OFF_STAGE + st * STAGE_STRIDE + A_LO_OFF;
        const uint32_t sB   = sbase + OFF_STAGE + st * STAGE_STRIDE + B_OFF;

        #pragma unroll
        for (int s = 0; s < 4; s++) {          // 4 k-steps of 16
            // ---- B fragments for this k-step: 4 n-chunks of 8 ----
            uint32_t bfr[4][2];
            {
                uint32_t t[4];
                int nrow = nb_base + b_nrow_in;
                int ch = 2 * s + b_ksel;
                ldsm_x4(t, sB + (uint32_t)nrow * 128 + (uint32_t)((ch ^ (nrow & 7)) << 4));
                bfr[0][0] = t[0]; bfr[0][1] = t[1];
                bfr[1][0] = t[2]; bfr[1][1] = t[3];
                nrow += 16;
                ldsm_x4(t, sB + (uint32_t)nrow * 128 + (uint32_t)((ch ^ (nrow & 7)) << 4));
                bfr[2][0] = t[0]; bfr[2][1] = t[1];
                bfr[3][0] = t[2]; bfr[3][1] = t[3];
            }
            // ---- A hi then A lo, 4 m-chunks of 16 ----
            #pragma unroll
            for (int mi = 0; mi < 4; mi++) {
                int arow = mrow_base + mi * 16 + a_row_in;
                int ch = 2 * s + a_ksel;
                uint32_t off = (uint32_t)arow * 128 + (uint32_t)((ch ^ (arow & 7)) << 4);
                uint32_t af[4];
                ldsm_x4(af, sAhi + off);
                #pragma unroll
                for (int ni = 0; ni < 4; ni++)
                    mma16816(acc[mi][ni], af, bfr[ni]);
                ldsm_x4(af, sAlo + off);
                #pragma unroll
                for (int ni = 0; ni < 4; ni++)
                    mma16816(acc[mi][ni], af, bfr[ni]);
            }
        }

        st = (st + 1 == STAGES) ? 0 : st + 1;
    }

    // -------- epilogue: out = scale*acc + biasS --------
    const float sc = scale_p[0];
    const float* bs = reinterpret_cast<const float*>(smem + OFF_BIAS);
    const int gr = lane >> 2;
    const int gc = (lane & 3) * 2;
    #pragma unroll
    for (int mi = 0; mi < 4; mi++) {
        const int r = m0 + wm * 64 + mi * 16 + gr;
        #pragma unroll
        for (int ni = 0; ni < 4; ni++) {
            const int cl = wn * 32 + ni * 8 + gc;   // local col in [0,128)
            const int c  = n0 + cl;
            float2 v;
            v.x = fmaf(sc, acc[mi][ni][0], bs[cl]);
            v.y = fmaf(sc, acc[mi][ni][1], bs[cl + 1]);
            *reinterpret_cast<float2*>(out + (size_t)r * Ndim + c) = v;
            v.x = fmaf(sc, acc[mi][ni][2], bs[cl]);
            v.y = fmaf(sc, acc[mi][ni][3], bs[cl + 1]);
            *reinterpret_cast<float2*>(out + (size_t)(r + 8) * Ndim + c) = v;
        }
    }
}

// ---------------- launch ----------------
extern "C" void kernel_launch(void* const* d_in, const int* in_sizes, int n_in,
                              void* d_out, int out_size) {
    const float* x   = (const float*)d_in[0];
    const int*   qw  = (const int*)d_in[1];
    const int*   qb  = (const int*)d_in[2];
    const float* sc  = (const float*)d_in[3];
    const float* bsc = (const float*)d_in[4];
    float* out = (float*)d_out;

    convert_w_kernel<<<1184, 256>>>(qw);
    convert_x_kernel<<<1184, 256>>>(x);

    static bool attr_set = false;
    cudaFuncSetAttribute(gemm_kernel, cudaFuncAttributeMaxDynamicSharedMemorySize, SMEM_TOTAL);
    (void)attr_set;

    dim3 grid(Ndim / BN, Mdim / BM); // (128, 64)
    gemm_kernel<<<grid, 256, SMEM_TOTAL>>>(qb, sc, bsc, out);
}